// round 1
// baseline (speedup 1.0000x reference)
#include <cuda_runtime.h>
#include <math.h>

#define TSTEPS 131072
#define ZD 64
#define XD 256
#define NCHUNK 512
#define CLEN 256        // TSTEPS / NCHUNK
#define LOG2_CLEN 8     // 2^8 = 256

__device__ __align__(16) float g_s[NCHUNK * ZD];     // chunk-local end states (zero init)
__device__ __align__(16) float g_init[NCHUNK * ZD];  // true init state per chunk
__device__ __align__(16) float g_AL[ZD * ZD];        // A^CLEN

// ---------------------------------------------------------------------------
// K0: A^CLEN via repeated squaring. One block, 256 threads.
// ---------------------------------------------------------------------------
__global__ void matpow_kernel(const float* __restrict__ A) {
    __shared__ float b0[ZD * ZD];
    __shared__ float b1[ZD * ZD];
    int tid = threadIdx.x;
    for (int e = tid; e < ZD * ZD; e += 256) b0[e] = A[e];
    __syncthreads();
    float* cur = b0;
    float* nxt = b1;
    for (int it = 0; it < LOG2_CLEN; ++it) {
        for (int e = tid; e < ZD * ZD; e += 256) {
            int i = e >> 6, j = e & 63;
            float acc = 0.f;
            #pragma unroll 8
            for (int k = 0; k < ZD; ++k) acc += cur[i * ZD + k] * cur[k * ZD + j];
            nxt[e] = acc;
        }
        __syncthreads();
        float* t = cur; cur = nxt; nxt = t;
    }
    for (int e = tid; e < ZD * ZD; e += 256) g_AL[e] = cur[e];
}

// ---------------------------------------------------------------------------
// Thread layout shared by the scan kernels (256 threads):
//   warp w (0..7), lane l: jg = l>>3 (quarter of the j range, 16 wide),
//   output row i = w*8 + (l&7). Four lanes cooperate per output row,
//   reduced with shfl_xor(8) + shfl_xor(16). Lanes l<8 are "writers".
// ---------------------------------------------------------------------------

// K1: chunk partials with zero init. Grid = NCHUNK blocks.
__global__ void __launch_bounds__(256) partial_kernel(
    const float* __restrict__ noise_z,
    const float* __restrict__ mu1,
    const float* __restrict__ Q1chol,
    const float* __restrict__ A,
    const float* __restrict__ Qchol)
{
    __shared__ __align__(16) float zsh[2][ZD];
    __shared__ __align__(16) float nzsh[2][ZD];
    const int c = blockIdx.x;
    const int t0 = c * CLEN;
    const int tid = threadIdx.x;
    const int w = tid >> 5, l = tid & 31;
    const int jg = l >> 3;
    const int i = w * 8 + (l & 7);
    const int jbase = jg * 16;

    float areg[16], qreg[16];
    #pragma unroll
    for (int q = 0; q < 4; ++q) {
        float4 av = *(const float4*)(A + i * ZD + jbase + 4 * q);
        areg[4*q+0] = av.x; areg[4*q+1] = av.y; areg[4*q+2] = av.z; areg[4*q+3] = av.w;
        float4 qv = *(const float4*)(Qchol + i * ZD + jbase + 4 * q);
        qreg[4*q+0] = qv.x; qreg[4*q+1] = qv.y; qreg[4*q+2] = qv.z; qreg[4*q+3] = qv.w;
    }
    if (tid < ZD) { zsh[0][tid] = 0.f; zsh[1][tid] = 0.f; }
    float4 rnz = make_float4(0.f, 0.f, 0.f, 0.f);
    if (tid < 16) {
        ((float4*)nzsh[0])[tid] = *(((const float4*)(noise_z + (size_t)t0 * ZD)) + tid);
        rnz = *(((const float4*)(noise_z + (size_t)(t0 + 1) * ZD)) + tid);
    }
    __syncthreads();

    int sb = 0;
    if (c == 0) {
        // peeled t=0: z0 = mu1 + Q1chol @ nz[0]
        float a0 = 0.f, a1 = 0.f, a2 = 0.f, a3 = 0.f;
        #pragma unroll
        for (int q = 0; q < 4; ++q) {
            float4 qv = *(const float4*)(Q1chol + i * ZD + jbase + 4 * q);
            float4 nv = ((const float4*)(nzsh[0] + jbase))[q];
            a0 += qv.x * nv.x; a1 += qv.y * nv.y; a2 += qv.z * nv.z; a3 += qv.w * nv.w;
        }
        float acc = (a0 + a1) + (a2 + a3);
        acc += __shfl_xor_sync(0xffffffffu, acc, 8);
        acc += __shfl_xor_sync(0xffffffffu, acc, 16);
        if (l < 8) zsh[0][i] = acc + mu1[i];
        if (tid < 16) {
            ((float4*)nzsh[1])[tid] = rnz;
            rnz = *(((const float4*)(noise_z + (size_t)(t0 + 2) * ZD)) + tid);
        }
        __syncthreads();
        sb = 1;
    }

    for (int s = sb; s < CLEN; ++s) {
        const int pa = s & 1, pb = pa ^ 1;
        const float* zp = zsh[pb] + jbase;
        const float* np = nzsh[pa] + jbase;
        float a0 = 0.f, a1 = 0.f, a2 = 0.f, a3 = 0.f;
        #pragma unroll
        for (int q = 0; q < 4; ++q) {
            float4 zv = ((const float4*)zp)[q];
            a0 += areg[4*q+0] * zv.x; a1 += areg[4*q+1] * zv.y;
            a2 += areg[4*q+2] * zv.z; a3 += areg[4*q+3] * zv.w;
            float4 nv = ((const float4*)np)[q];
            a0 += qreg[4*q+0] * nv.x; a1 += qreg[4*q+1] * nv.y;
            a2 += qreg[4*q+2] * nv.z; a3 += qreg[4*q+3] * nv.w;
        }
        float acc = (a0 + a1) + (a2 + a3);
        acc += __shfl_xor_sync(0xffffffffu, acc, 8);
        acc += __shfl_xor_sync(0xffffffffu, acc, 16);
        if (l < 8) zsh[pa][i] = acc;
        if (tid < 16) {
            if (s + 1 < CLEN) ((float4*)nzsh[pb])[tid] = rnz;
            if (s + 2 < CLEN) rnz = *(((const float4*)(noise_z + (size_t)(t0 + s + 2) * ZD)) + tid);
        }
        __syncthreads();
    }
    if (tid < ZD) g_s[c * ZD + tid] = zsh[(CLEN - 1) & 1][tid];
}

// K2: sequential boundary scan. h_c = A^CLEN * h_{c-1} + s_c ; g_init[c] = h_{c-1}.
__global__ void __launch_bounds__(256) boundary_kernel() {
    __shared__ __align__(16) float hsh[2][ZD];
    const int tid = threadIdx.x;
    const int w = tid >> 5, l = tid & 31;
    const int jg = l >> 3;
    const int i = w * 8 + (l & 7);
    const int jbase = jg * 16;

    float alreg[16];
    #pragma unroll
    for (int q = 0; q < 4; ++q) {
        float4 av = *(const float4*)(g_AL + i * ZD + jbase + 4 * q);
        alreg[4*q+0] = av.x; alreg[4*q+1] = av.y; alreg[4*q+2] = av.z; alreg[4*q+3] = av.w;
    }
    if (tid < ZD) { hsh[0][tid] = 0.f; hsh[1][tid] = 0.f; }
    float s0 = 0.f, s1 = 0.f, hreg = 0.f;
    if (l < 8) { s0 = g_s[i]; s1 = g_s[ZD + i]; }
    __syncthreads();

    for (int cc = 0; cc < NCHUNK; ++cc) {
        const int pa = cc & 1, pb = pa ^ 1;
        const float* hp = hsh[pb] + jbase;
        float a0 = 0.f, a1 = 0.f, a2 = 0.f, a3 = 0.f;
        #pragma unroll
        for (int q = 0; q < 4; ++q) {
            float4 hv = ((const float4*)hp)[q];
            a0 += alreg[4*q+0] * hv.x; a1 += alreg[4*q+1] * hv.y;
            a2 += alreg[4*q+2] * hv.z; a3 += alreg[4*q+3] * hv.w;
        }
        float acc = (a0 + a1) + (a2 + a3);
        acc += __shfl_xor_sync(0xffffffffu, acc, 8);
        acc += __shfl_xor_sync(0xffffffffu, acc, 16);
        if (l < 8) {
            g_init[cc * ZD + i] = hreg;
            float hn = acc + s0;
            hsh[pa][i] = hn;
            hreg = hn;
            s0 = s1;
            s1 = (cc + 2 < NCHUNK) ? g_s[(cc + 2) * ZD + i] : 0.f;
        }
        __syncthreads();
    }
}

// K3: final pass — re-run recurrence from true init, fused emission to out.
__global__ void __launch_bounds__(256) final_kernel(
    const float* __restrict__ noise_z,
    const float* __restrict__ noise_x,
    const float* __restrict__ mu1,
    const float* __restrict__ Q1chol,
    const float* __restrict__ A,
    const float* __restrict__ Qchol,
    const float* __restrict__ Rchol,
    const float* __restrict__ W,
    const float* __restrict__ bvec,
    float* __restrict__ out)
{
    __shared__ __align__(16) float zsh[2][ZD];
    __shared__ __align__(16) float nzsh[2][ZD];
    const int c = blockIdx.x;
    const int t0 = c * CLEN;
    const int tid = threadIdx.x;
    const int w = tid >> 5, l = tid & 31;
    const int jg = l >> 3;
    const int i = w * 8 + (l & 7);
    const int jbase = jg * 16;

    float areg[16], qreg[16];
    #pragma unroll
    for (int q = 0; q < 4; ++q) {
        float4 av = *(const float4*)(A + i * ZD + jbase + 4 * q);
        areg[4*q+0] = av.x; areg[4*q+1] = av.y; areg[4*q+2] = av.z; areg[4*q+3] = av.w;
        float4 qv = *(const float4*)(Qchol + i * ZD + jbase + 4 * q);
        qreg[4*q+0] = qv.x; qreg[4*q+1] = qv.y; qreg[4*q+2] = qv.z; qreg[4*q+3] = qv.w;
    }
    float wreg[ZD];
    #pragma unroll
    for (int k = 0; k < ZD; ++k) wreg[k] = W[k * XD + tid];
    const float breg = bvec[tid];
    const float rr = fabsf(Rchol[tid]);
    float rnx = noise_x[(size_t)t0 * XD + tid];

    if (tid < ZD) {
        zsh[1][tid] = g_init[c * ZD + tid];  // true init (z_{t0-1}); zeros for c==0
        zsh[0][tid] = 0.f;
    }
    float4 rnz = make_float4(0.f, 0.f, 0.f, 0.f);
    if (tid < 16) {
        ((float4*)nzsh[0])[tid] = *(((const float4*)(noise_z + (size_t)t0 * ZD)) + tid);
        rnz = *(((const float4*)(noise_z + (size_t)(t0 + 1) * ZD)) + tid);
    }
    __syncthreads();

    int sb = 0;
    if (c == 0) {
        // peeled t=0: z0 = mu1 + Q1chol @ nz[0]  (g_init[0] == 0)
        float a0 = 0.f, a1 = 0.f, a2 = 0.f, a3 = 0.f;
        #pragma unroll
        for (int q = 0; q < 4; ++q) {
            float4 qv = *(const float4*)(Q1chol + i * ZD + jbase + 4 * q);
            float4 nv = ((const float4*)(nzsh[0] + jbase))[q];
            a0 += qv.x * nv.x; a1 += qv.y * nv.y; a2 += qv.z * nv.z; a3 += qv.w * nv.w;
        }
        float acc = (a0 + a1) + (a2 + a3);
        acc += __shfl_xor_sync(0xffffffffu, acc, 8);
        acc += __shfl_xor_sync(0xffffffffu, acc, 16);
        if (l < 8) zsh[0][i] = acc + mu1[i];
        if (tid < 16) {
            ((float4*)nzsh[1])[tid] = rnz;
            rnz = *(((const float4*)(noise_z + (size_t)(t0 + 2) * ZD)) + tid);
        }
        __syncthreads();
        // emission for t=0
        {
            const float* zc = zsh[0];
            float x0 = 0.f, x1 = 0.f, x2 = 0.f, x3 = 0.f;
            #pragma unroll
            for (int k4 = 0; k4 < 16; ++k4) {
                float4 zv = ((const float4*)zc)[k4];
                x0 += wreg[4*k4+0] * zv.x; x1 += wreg[4*k4+1] * zv.y;
                x2 += wreg[4*k4+2] * zv.z; x3 += wreg[4*k4+3] * zv.w;
            }
            float nx = rnx;
            rnx = noise_x[(size_t)(t0 + 1) * XD + tid];
            out[(size_t)t0 * XD + tid] = ((x0 + x1) + (x2 + x3)) + breg + nx * rr;
        }
        sb = 1;
    }

    for (int s = sb; s < CLEN; ++s) {
        const int pa = s & 1, pb = pa ^ 1;
        // phase 1: z_t = A z_{t-1} + Qchol nz[t]
        {
            const float* zp = zsh[pb] + jbase;
            const float* np = nzsh[pa] + jbase;
            float a0 = 0.f, a1 = 0.f, a2 = 0.f, a3 = 0.f;
            #pragma unroll
            for (int q = 0; q < 4; ++q) {
                float4 zv = ((const float4*)zp)[q];
                a0 += areg[4*q+0] * zv.x; a1 += areg[4*q+1] * zv.y;
                a2 += areg[4*q+2] * zv.z; a3 += areg[4*q+3] * zv.w;
                float4 nv = ((const float4*)np)[q];
                a0 += qreg[4*q+0] * nv.x; a1 += qreg[4*q+1] * nv.y;
                a2 += qreg[4*q+2] * nv.z; a3 += qreg[4*q+3] * nv.w;
            }
            float acc = (a0 + a1) + (a2 + a3);
            acc += __shfl_xor_sync(0xffffffffu, acc, 8);
            acc += __shfl_xor_sync(0xffffffffu, acc, 16);
            if (l < 8) zsh[pa][i] = acc;
            if (tid < 16) {
                if (s + 1 < CLEN) ((float4*)nzsh[pb])[tid] = rnz;
                if (s + 2 < CLEN) rnz = *(((const float4*)(noise_z + (size_t)(t0 + s + 2) * ZD)) + tid);
            }
        }
        __syncthreads();
        // phase 2: emission x_t = z_t @ W + b + |R| * nx
        {
            const float* zc = zsh[pa];
            float x0 = 0.f, x1 = 0.f, x2 = 0.f, x3 = 0.f;
            #pragma unroll
            for (int k4 = 0; k4 < 16; ++k4) {
                float4 zv = ((const float4*)zc)[k4];
                x0 += wreg[4*k4+0] * zv.x; x1 += wreg[4*k4+1] * zv.y;
                x2 += wreg[4*k4+2] * zv.z; x3 += wreg[4*k4+3] * zv.w;
            }
            float nx = rnx;
            if (s + 1 < CLEN) rnx = noise_x[(size_t)(t0 + s + 1) * XD + tid];
            out[(size_t)(t0 + s) * XD + tid] = ((x0 + x1) + (x2 + x3)) + breg + nx * rr;
        }
        // no trailing barrier needed: next phase1 writes zsh[pb]/nzsh[pa], which
        // this step's phase2 never reads; ordering across steps is provided by
        // the single barrier between phase1 and phase2.
    }
}

extern "C" void kernel_launch(void* const* d_in, const int* in_sizes, int n_in,
                              void* d_out, int out_size) {
    const float* noise_z = (const float*)d_in[0];
    const float* noise_x = (const float*)d_in[1];
    const float* mu1     = (const float*)d_in[2];
    const float* Q1chol  = (const float*)d_in[3];
    const float* A       = (const float*)d_in[4];
    const float* Qchol   = (const float*)d_in[5];
    const float* Rchol   = (const float*)d_in[6];
    const float* W       = (const float*)d_in[7];
    const float* bvec    = (const float*)d_in[8];
    float* out = (float*)d_out;

    matpow_kernel<<<1, 256>>>(A);
    partial_kernel<<<NCHUNK, 256>>>(noise_z, mu1, Q1chol, A, Qchol);
    boundary_kernel<<<1, 256>>>();
    final_kernel<<<NCHUNK, 256>>>(noise_z, noise_x, mu1, Q1chol, A, Qchol,
                                  Rchol, W, bvec, out);
}

// round 2
// speedup vs baseline: 2.0049x; 2.0049x over previous
#include <cuda_runtime.h>
#include <math.h>

#define T_ALL  131072
#define ZD     64
#define XD     256
#define BM     16               // batch length for the fine scan
#define NB     (T_ALL / BM)     // 8192 batches
#define GRP    64               // batches per group
#define NG     (NB / GRP)       // 128 groups
#define NBLK_U (T_ALL / 64)     // 2048 u-GEMM blocks

// scratch (static device allocations are allowed)
__device__ __align__(16) float g_u[(size_t)T_ALL * ZD];   // injections u_t
__device__ __align__(16) float g_z[(size_t)T_ALL * ZD];   // latent states
__device__ __align__(16) float g_s[NB * ZD];              // batch partials (zero-init)
__device__ __align__(16) float g_H[NB * ZD];              // true init state per batch
__device__ __align__(16) float g_Sg[NG * ZD];             // group partials
__device__ __align__(16) float g_Gg[NG * ZD];             // true init per group
__device__ __align__(16) float g_A16[ZD * ZD];
__device__ __align__(16) float g_A1024[ZD * ZD];

// ---------------------------------------------------------------------------
// K0+K1 fused: block NBLK_U computes A^16 and A^1024 (10 squarings);
// blocks 0..NBLK_U-1 compute u[t] = Qchol @ n_t  (t=0 special-cased in block 0:
// u[0] = mu1 + Q1chol @ n_0, which makes z_t = A z_{t-1} + u_t uniform, z_{-1}=0).
// ---------------------------------------------------------------------------
__global__ void __launch_bounds__(256) k01_kernel(
    const float* __restrict__ nz, const float* __restrict__ mu1,
    const float* __restrict__ Q1, const float* __restrict__ A,
    const float* __restrict__ Qc)
{
    __shared__ __align__(16) float pool[4096 + 64 * 68];
    const int tid = threadIdx.x;

    if (blockIdx.x == NBLK_U) {
        // ---- matpow: A^(2^it) by repeated squaring, ping-pong in shared ----
        float* cur = pool;
        float* nxt = pool + 4096;
        for (int e = tid; e < 4096; e += 256) cur[e] = A[e];
        __syncthreads();
        for (int it = 0; it < 10; ++it) {
            for (int e = tid; e < 4096; e += 256) {
                const int i = e >> 6, j = e & 63;
                float a0 = 0.f, a1 = 0.f, a2 = 0.f, a3 = 0.f;
                #pragma unroll
                for (int k = 0; k < 64; k += 4) {
                    a0 += cur[i * 64 + k    ] * cur[(k    ) * 64 + j];
                    a1 += cur[i * 64 + k + 1] * cur[(k + 1) * 64 + j];
                    a2 += cur[i * 64 + k + 2] * cur[(k + 2) * 64 + j];
                    a3 += cur[i * 64 + k + 3] * cur[(k + 3) * 64 + j];
                }
                nxt[e] = (a0 + a1) + (a2 + a3);
            }
            __syncthreads();
            float* t = cur; cur = nxt; nxt = t;
            if (it == 3)
                for (int e = tid; e < 4096; e += 256) g_A16[e] = cur[e];
        }
        for (int e = tid; e < 4096; e += 256) g_A1024[e] = cur[e];
        return;
    }

    // ---- u-GEMM: 64 timesteps per block ----
    float* sn  = pool;          // n tile [t][k], 64x64
    float* sqT = pool + 4096;   // Qchol^T [k][i], row stride 68 (pad: aligned, low-conflict)
    const int tb = blockIdx.x;
    const float4* nsrc = (const float4*)(nz + (size_t)tb * 4096);
    for (int e4 = tid; e4 < 1024; e4 += 256) ((float4*)sn)[e4] = nsrc[e4];
    for (int e = tid; e < 4096; e += 256) {
        const int i = e >> 6, k = e & 63;
        sqT[k * 68 + i] = Qc[e];
    }
    __syncthreads();

    const int tx = tid & 15, ty = tid >> 4;
    const int i0 = tx * 4, t0 = ty * 4;
    float acc[4][4];
    #pragma unroll
    for (int a = 0; a < 4; ++a)
        #pragma unroll
        for (int c = 0; c < 4; ++c) acc[a][c] = 0.f;

    #pragma unroll 4
    for (int k0 = 0; k0 < 64; k0 += 4) {
        float4 nv[4];
        #pragma unroll
        for (int tt = 0; tt < 4; ++tt)
            nv[tt] = *(const float4*)&sn[(t0 + tt) * 64 + k0];
        #pragma unroll
        for (int kk = 0; kk < 4; ++kk) {
            const float4 qv = *(const float4*)&sqT[(k0 + kk) * 68 + i0];
            #pragma unroll
            for (int tt = 0; tt < 4; ++tt) {
                const float zs = (kk == 0) ? nv[tt].x : (kk == 1) ? nv[tt].y
                               : (kk == 2) ? nv[tt].z : nv[tt].w;
                acc[tt][0] += zs * qv.x; acc[tt][1] += zs * qv.y;
                acc[tt][2] += zs * qv.z; acc[tt][3] += zs * qv.w;
            }
        }
    }

    if (tb == 0 && ty == 0) {
        // overwrite t=0: u0 = mu1 + Q1chol @ n0   (sn row 0 holds n0)
        #pragma unroll
        for (int ii = 0; ii < 4; ++ii) {
            float s = mu1[i0 + ii];
            for (int k = 0; k < 64; ++k) s += Q1[(i0 + ii) * 64 + k] * sn[k];
            acc[0][ii] = s;
        }
    }

    #pragma unroll
    for (int tt = 0; tt < 4; ++tt) {
        float4 v = make_float4(acc[tt][0], acc[tt][1], acc[tt][2], acc[tt][3]);
        *(float4*)&g_u[((size_t)tb * 64 + t0 + tt) * 64 + i0] = v;
    }
}

// ---------------------------------------------------------------------------
// K2a: batch partials from zero init. 4 batches per block (64 threads each,
// one thread per z-row, A row in registers, z ping-pong in shared).
// ---------------------------------------------------------------------------
__global__ void __launch_bounds__(256) partial16_kernel(const float* __restrict__ A)
{
    __shared__ __align__(16) float zsh[4][2][ZD];
    const int tid = threadIdx.x;
    const int grp = tid >> 6, i = tid & 63;
    const int b = blockIdx.x * 4 + grp;

    float areg[64];
    #pragma unroll
    for (int q = 0; q < 16; ++q) {
        const float4 v = *(const float4*)&A[i * 64 + q * 4];
        areg[4*q] = v.x; areg[4*q+1] = v.y; areg[4*q+2] = v.z; areg[4*q+3] = v.w;
    }
    zsh[grp][0][i] = 0.f;
    float unext = g_u[((size_t)b * BM) * 64 + i];
    __syncthreads();

    #pragma unroll 2
    for (int j = 0; j < BM; ++j) {
        const float uc = unext;
        if (j < BM - 1) unext = g_u[((size_t)b * BM + j + 1) * 64 + i];
        const float* zp = zsh[grp][j & 1];
        float a0 = 0.f, a1 = 0.f, a2 = 0.f, a3 = 0.f;
        #pragma unroll
        for (int q = 0; q < 16; ++q) {
            const float4 zv = *(const float4*)&zp[4 * q];
            a0 += areg[4*q] * zv.x;   a1 += areg[4*q+1] * zv.y;
            a2 += areg[4*q+2] * zv.z; a3 += areg[4*q+3] * zv.w;
        }
        zsh[grp][(j & 1) ^ 1][i] = ((a0 + a1) + (a2 + a3)) + uc;
        __syncthreads();
    }
    g_s[(size_t)b * 64 + i] = zsh[grp][0][i];   // BM even -> result in buffer 0
}

// ---------------------------------------------------------------------------
// K2b1: group partials (zero init) over 64 batch-boundaries with A^16.
// ---------------------------------------------------------------------------
__global__ void __launch_bounds__(64) grp_partial_kernel()
{
    __shared__ __align__(16) float hsh[2][ZD];
    const int i = threadIdx.x, g = blockIdx.x;
    float areg[64];
    #pragma unroll
    for (int q = 0; q < 16; ++q) {
        const float4 v = *(const float4*)&g_A16[i * 64 + q * 4];
        areg[4*q] = v.x; areg[4*q+1] = v.y; areg[4*q+2] = v.z; areg[4*q+3] = v.w;
    }
    hsh[0][i] = 0.f;
    float snext = g_s[((size_t)g * GRP) * 64 + i];
    __syncthreads();
    for (int j = 0; j < GRP; ++j) {
        const float sc = snext;
        if (j < GRP - 1) snext = g_s[((size_t)g * GRP + j + 1) * 64 + i];
        const float* hp = hsh[j & 1];
        float a0 = 0.f, a1 = 0.f, a2 = 0.f, a3 = 0.f;
        #pragma unroll
        for (int q = 0; q < 16; ++q) {
            const float4 hv = *(const float4*)&hp[4 * q];
            a0 += areg[4*q] * hv.x;   a1 += areg[4*q+1] * hv.y;
            a2 += areg[4*q+2] * hv.z; a3 += areg[4*q+3] * hv.w;
        }
        hsh[(j & 1) ^ 1][i] = ((a0 + a1) + (a2 + a3)) + sc;
        __syncthreads();
    }
    g_Sg[g * 64 + i] = hsh[0][i];
}

// ---------------------------------------------------------------------------
// K2b2: sequential scan over 128 groups with A^1024; records group inits.
// ---------------------------------------------------------------------------
__global__ void __launch_bounds__(64) grp_scan_kernel()
{
    __shared__ __align__(16) float hsh[2][ZD];
    const int i = threadIdx.x;
    float areg[64];
    #pragma unroll
    for (int q = 0; q < 16; ++q) {
        const float4 v = *(const float4*)&g_A1024[i * 64 + q * 4];
        areg[4*q] = v.x; areg[4*q+1] = v.y; areg[4*q+2] = v.z; areg[4*q+3] = v.w;
    }
    hsh[0][i] = 0.f;
    float snext = g_Sg[i];
    __syncthreads();
    for (int g = 0; g < NG; ++g) {
        g_Gg[g * 64 + i] = hsh[g & 1][i];
        const float sc = snext;
        if (g < NG - 1) snext = g_Sg[(g + 1) * 64 + i];
        const float* hp = hsh[g & 1];
        float a0 = 0.f, a1 = 0.f, a2 = 0.f, a3 = 0.f;
        #pragma unroll
        for (int q = 0; q < 16; ++q) {
            const float4 hv = *(const float4*)&hp[4 * q];
            a0 += areg[4*q] * hv.x;   a1 += areg[4*q+1] * hv.y;
            a2 += areg[4*q+2] * hv.z; a3 += areg[4*q+3] * hv.w;
        }
        hsh[(g & 1) ^ 1][i] = ((a0 + a1) + (a2 + a3)) + sc;
        __syncthreads();
    }
}

// ---------------------------------------------------------------------------
// K2b3: expand within group -> true init state for every batch (g_H).
// ---------------------------------------------------------------------------
__global__ void __launch_bounds__(64) grp_expand_kernel()
{
    __shared__ __align__(16) float hsh[2][ZD];
    const int i = threadIdx.x, g = blockIdx.x;
    float areg[64];
    #pragma unroll
    for (int q = 0; q < 16; ++q) {
        const float4 v = *(const float4*)&g_A16[i * 64 + q * 4];
        areg[4*q] = v.x; areg[4*q+1] = v.y; areg[4*q+2] = v.z; areg[4*q+3] = v.w;
    }
    hsh[0][i] = g_Gg[g * 64 + i];
    float snext = g_s[((size_t)g * GRP) * 64 + i];
    __syncthreads();
    for (int j = 0; j < GRP; ++j) {
        const int b = g * GRP + j;
        g_H[(size_t)b * 64 + i] = hsh[j & 1][i];
        const float sc = snext;
        if (j < GRP - 1) snext = g_s[((size_t)b + 1) * 64 + i];
        const float* hp = hsh[j & 1];
        float a0 = 0.f, a1 = 0.f, a2 = 0.f, a3 = 0.f;
        #pragma unroll
        for (int q = 0; q < 16; ++q) {
            const float4 hv = *(const float4*)&hp[4 * q];
            a0 += areg[4*q] * hv.x;   a1 += areg[4*q+1] * hv.y;
            a2 += areg[4*q+2] * hv.z; a3 += areg[4*q+3] * hv.w;
        }
        hsh[(j & 1) ^ 1][i] = ((a0 + a1) + (a2 + a3)) + sc;
        __syncthreads();
    }
}

// ---------------------------------------------------------------------------
// K3: expand batches from true init, write all z_t to g_z.
// ---------------------------------------------------------------------------
__global__ void __launch_bounds__(256) expand16_kernel(const float* __restrict__ A)
{
    __shared__ __align__(16) float zsh[4][2][ZD];
    const int tid = threadIdx.x;
    const int grp = tid >> 6, i = tid & 63;
    const int b = blockIdx.x * 4 + grp;

    float areg[64];
    #pragma unroll
    for (int q = 0; q < 16; ++q) {
        const float4 v = *(const float4*)&A[i * 64 + q * 4];
        areg[4*q] = v.x; areg[4*q+1] = v.y; areg[4*q+2] = v.z; areg[4*q+3] = v.w;
    }
    zsh[grp][0][i] = g_H[(size_t)b * 64 + i];
    float unext = g_u[((size_t)b * BM) * 64 + i];
    __syncthreads();

    #pragma unroll 2
    for (int j = 0; j < BM; ++j) {
        const float uc = unext;
        if (j < BM - 1) unext = g_u[((size_t)b * BM + j + 1) * 64 + i];
        const float* zp = zsh[grp][j & 1];
        float a0 = 0.f, a1 = 0.f, a2 = 0.f, a3 = 0.f;
        #pragma unroll
        for (int q = 0; q < 16; ++q) {
            const float4 zv = *(const float4*)&zp[4 * q];
            a0 += areg[4*q] * zv.x;   a1 += areg[4*q+1] * zv.y;
            a2 += areg[4*q+2] * zv.z; a3 += areg[4*q+3] * zv.w;
        }
        const float res = ((a0 + a1) + (a2 + a3)) + uc;
        zsh[grp][(j & 1) ^ 1][i] = res;
        g_z[((size_t)b * BM + j) * 64 + i] = res;
        __syncthreads();
    }
}

// ---------------------------------------------------------------------------
// K4: emission GEMM  x = z @ W + b + |R| * nx.  64t x 256j tile per block,
// 8t x 8j per thread (two j-quads), W resident in shared (64 KB, dynamic).
// ---------------------------------------------------------------------------
__global__ void __launch_bounds__(256, 2) emis_kernel(
    const float* __restrict__ nx, const float* __restrict__ Rc,
    const float* __restrict__ W, const float* __restrict__ bvec,
    float* __restrict__ out)
{
    extern __shared__ float dsm[];
    float* sw = dsm;              // [k][j]  64x256
    float* sz = dsm + 64 * 256;   // [t][k]  64x64
    const int tid = threadIdx.x;
    const size_t t0b = (size_t)blockIdx.x * 64;

    for (int e4 = tid; e4 < 4096; e4 += 256) ((float4*)sw)[e4] = ((const float4*)W)[e4];
    {
        const float4* zsrc = (const float4*)(g_z + t0b * 64);
        for (int e4 = tid; e4 < 1024; e4 += 256) ((float4*)sz)[e4] = zsrc[e4];
    }
    __syncthreads();

    const int jx = tid & 31, ty = tid >> 5;
    const int jA = jx * 4, jB = 128 + jx * 4;
    const int tA = ty * 8;

    float accA[8][4], accB[8][4];
    #pragma unroll
    for (int a = 0; a < 8; ++a)
        #pragma unroll
        for (int c = 0; c < 4; ++c) { accA[a][c] = 0.f; accB[a][c] = 0.f; }

    #pragma unroll 4
    for (int k0 = 0; k0 < 64; k0 += 4) {
        float4 zt[8];
        #pragma unroll
        for (int tt = 0; tt < 8; ++tt)
            zt[tt] = *(const float4*)&sz[(tA + tt) * 64 + k0];
        #pragma unroll
        for (int kk = 0; kk < 4; ++kk) {
            const float4 wA = *(const float4*)&sw[(k0 + kk) * 256 + jA];
            const float4 wB = *(const float4*)&sw[(k0 + kk) * 256 + jB];
            #pragma unroll
            for (int tt = 0; tt < 8; ++tt) {
                const float zs = (kk == 0) ? zt[tt].x : (kk == 1) ? zt[tt].y
                               : (kk == 2) ? zt[tt].z : zt[tt].w;
                accA[tt][0] += zs * wA.x; accA[tt][1] += zs * wA.y;
                accA[tt][2] += zs * wA.z; accA[tt][3] += zs * wA.w;
                accB[tt][0] += zs * wB.x; accB[tt][1] += zs * wB.y;
                accB[tt][2] += zs * wB.z; accB[tt][3] += zs * wB.w;
            }
        }
    }

    float4 bA = *(const float4*)&bvec[jA], bB = *(const float4*)&bvec[jB];
    float4 rA = *(const float4*)&Rc[jA],  rB = *(const float4*)&Rc[jB];
    rA.x = fabsf(rA.x); rA.y = fabsf(rA.y); rA.z = fabsf(rA.z); rA.w = fabsf(rA.w);
    rB.x = fabsf(rB.x); rB.y = fabsf(rB.y); rB.z = fabsf(rB.z); rB.w = fabsf(rB.w);

    #pragma unroll
    for (int tt = 0; tt < 8; ++tt) {
        const size_t t = t0b + tA + tt;
        const float4 nA = *(const float4*)&nx[t * XD + jA];
        const float4 nB = *(const float4*)&nx[t * XD + jB];
        float4 oA, oB;
        oA.x = accA[tt][0] + bA.x + rA.x * nA.x;
        oA.y = accA[tt][1] + bA.y + rA.y * nA.y;
        oA.z = accA[tt][2] + bA.z + rA.z * nA.z;
        oA.w = accA[tt][3] + bA.w + rA.w * nA.w;
        oB.x = accB[tt][0] + bB.x + rB.x * nB.x;
        oB.y = accB[tt][1] + bB.y + rB.y * nB.y;
        oB.z = accB[tt][2] + bB.z + rB.z * nB.z;
        oB.w = accB[tt][3] + bB.w + rB.w * nB.w;
        *(float4*)&out[t * XD + jA] = oA;
        *(float4*)&out[t * XD + jB] = oB;
    }
}

extern "C" void kernel_launch(void* const* d_in, const int* in_sizes, int n_in,
                              void* d_out, int out_size) {
    const float* noise_z = (const float*)d_in[0];
    const float* noise_x = (const float*)d_in[1];
    const float* mu1     = (const float*)d_in[2];
    const float* Q1chol  = (const float*)d_in[3];
    const float* A       = (const float*)d_in[4];
    const float* Qchol   = (const float*)d_in[5];
    const float* Rchol   = (const float*)d_in[6];
    const float* W       = (const float*)d_in[7];
    const float* bvec    = (const float*)d_in[8];
    float* out = (float*)d_out;

    const int emis_smem = (64 * 256 + 64 * 64) * 4;  // 80 KB dynamic
    cudaFuncSetAttribute(emis_kernel, cudaFuncAttributeMaxDynamicSharedMemorySize, emis_smem);

    k01_kernel<<<NBLK_U + 1, 256>>>(noise_z, mu1, Q1chol, A, Qchol);
    partial16_kernel<<<NB / 4, 256>>>(A);
    grp_partial_kernel<<<NG, 64>>>();
    grp_scan_kernel<<<1, 64>>>();
    grp_expand_kernel<<<NG, 64>>>();
    expand16_kernel<<<NB / 4, 256>>>(A);
    emis_kernel<<<T_ALL / 64, 256, emis_smem>>>(noise_x, Rchol, W, bvec, out);
}